// round 1
// baseline (speedup 1.0000x reference)
#include <cuda_runtime.h>
#include <math.h>

// ---------------------------------------------------------------------------
// CombinedElevationEncoder — fused GB300/B200 implementation
//
// Insight 1: the dual-CNN branch is only consumed through a (4,4) block-mean
//            pool -> fuse conv1+relu+conv2+relu+pool, never hit GMEM with
//            activations.
// Insight 2: the spiking Conv2dLSTM emits spike(mem-1) with mem = sig(o)*tanh(syn)
//            which is <= 1.0 even under fp rounding -> all spikes are exactly 0,
//            sconv_ctx == 0, sconv_res == b_proj. The whole T=128 scan is skipped.
// ---------------------------------------------------------------------------

#define BATCH 32
#define HH    128
#define WW    1536
#define TH    8          // conv tile height (output rows per block)
#define TW    64         // conv tile width
#define GX    (WW / TW)  // 24
#define GY    (HH / TH)  // 16
#define NCONTRIB 24      // (32/TH)*(384/TW) = 4*6 contributing blocks per pool cell

// partial pooled sums: [b][oc][ph][pw][contrib]
__device__ float g_partial[BATCH * 8 * 4 * 4 * NCONTRIB];

// ---------------------------------------------------------------------------
// Fused conv1(2->8, 5x7, pad 2,3) + ReLU + conv2(8->8, 3x5, pad 1,2) + ReLU
// + partial (4,4) pool sums.
// ---------------------------------------------------------------------------
__global__ __launch_bounds__(256)
void conv_fused_kernel(const float* __restrict__ x,      // [B,2,H,W]
                       const float* __restrict__ w1,     // [8,2,5,7]
                       const float* __restrict__ b1,     // [8]
                       const float* __restrict__ w2,     // [8,8,3,5]
                       const float* __restrict__ b2)     // [8]
{
    // input tile: rows [h0, h0+14), cols [w0, w0+74)
    __shared__ __align__(16) float sIn[2][14][76];
    // conv1 tile: 8ch x 10 rows x 68 cols (stride 72)
    __shared__ __align__(16) float sC1[8][10][72];
    // weights repacked as [ic][kh][kw][oc] (oc contiguous -> 2x LDS.128 per tap)
    __shared__ __align__(16) float sW1[2 * 5 * 7 * 8];   // 560
    __shared__ __align__(16) float sW2[8 * 3 * 5 * 8];   // 960
    __shared__ float sB1[8], sB2[8];
    __shared__ float sRed[8][8];                         // [warp][oc]

    const int tid = threadIdx.x;
    const int bx = blockIdx.x, by = blockIdx.y, b = blockIdx.z;
    const int h0 = by * TH - 3;   // conv2 needs conv1 rows -1..+1, conv1 needs in rows -2..+2
    const int w0 = bx * TW - 5;

    // ---- repack weights into smem ----
    for (int idx = tid; idx < 560; idx += 256) {
        int oc = idx & 7; int t = idx >> 3;
        int kw = t % 7; t /= 7;
        int kh = t % 5; int ic = t / 5;
        sW1[idx] = w1[((oc * 2 + ic) * 5 + kh) * 7 + kw];
    }
    for (int idx = tid; idx < 960; idx += 256) {
        int oc = idx & 7; int t = idx >> 3;
        int kw = t % 5; t /= 5;
        int kh = t % 3; int ic = t / 3;
        sW2[idx] = w2[((oc * 8 + ic) * 3 + kh) * 5 + kw];
    }
    if (tid < 8) { sB1[tid] = b1[tid]; sB2[tid] = b2[tid]; }

    // ---- load input tile (zero-padded at borders) ----
    const float* xb = x + (size_t)b * 2 * HH * WW;
    for (int idx = tid; idx < 2 * 14 * 74; idx += 256) {
        int c = idx % 74; int t = idx / 74;
        int r = t % 14; int ic = t / 14;
        int gh = h0 + r, gw = w0 + c;
        float v = 0.f;
        if (gh >= 0 && gh < HH && gw >= 0 && gw < WW)
            v = xb[(ic * HH + gh) * WW + gw];
        sIn[ic][r][c] = v;
    }
    __syncthreads();

    // ---- conv1 + ReLU: 10 rows x 68 cols x 8ch; 4 cols per thread ----
    if (tid < 170) {                       // 10 rows * 17 col-groups
        const int r  = tid / 17;
        const int c0 = (tid % 17) * 4;
        float acc[8][4];
        #pragma unroll
        for (int oc = 0; oc < 8; oc++) {
            float bb = sB1[oc];
            acc[oc][0] = bb; acc[oc][1] = bb; acc[oc][2] = bb; acc[oc][3] = bb;
        }
        #pragma unroll
        for (int ic = 0; ic < 2; ic++) {
            #pragma unroll
            for (int kh = 0; kh < 5; kh++) {
                const float* rp = &sIn[ic][r + kh][c0];
                float4 q0 = *(const float4*)rp;
                float4 q1 = *(const float4*)(rp + 4);
                float2 q2 = *(const float2*)(rp + 8);
                float v[10] = {q0.x, q0.y, q0.z, q0.w,
                               q1.x, q1.y, q1.z, q1.w,
                               q2.x, q2.y};
                #pragma unroll
                for (int kw = 0; kw < 7; kw++) {
                    const float4* wp = (const float4*)&sW1[((ic * 5 + kh) * 7 + kw) * 8];
                    float4 wa = wp[0], wb = wp[1];
                    float wv[8] = {wa.x, wa.y, wa.z, wa.w, wb.x, wb.y, wb.z, wb.w};
                    #pragma unroll
                    for (int oc = 0; oc < 8; oc++) {
                        #pragma unroll
                        for (int p = 0; p < 4; p++)
                            acc[oc][p] = fmaf(v[kw + p], wv[oc], acc[oc][p]);
                    }
                }
            }
        }
        #pragma unroll
        for (int oc = 0; oc < 8; oc++) {
            float4 o;
            o.x = fmaxf(acc[oc][0], 0.f);
            o.y = fmaxf(acc[oc][1], 0.f);
            o.z = fmaxf(acc[oc][2], 0.f);
            o.w = fmaxf(acc[oc][3], 0.f);
            *(float4*)&sC1[oc][r][c0] = o;
        }
    }
    __syncthreads();

    // ---- conv2 + ReLU + pool partial: 8 rows x 64 cols; 2 cols/thread ----
    {
        const int row = tid >> 5;            // 0..7
        const int c0  = (tid & 31) * 2;      // 0..62
        float acc[8][2];
        #pragma unroll
        for (int oc = 0; oc < 8; oc++) {
            float bb = sB2[oc]; acc[oc][0] = bb; acc[oc][1] = bb;
        }
        #pragma unroll
        for (int ic = 0; ic < 8; ic++) {
            #pragma unroll
            for (int kh = 0; kh < 3; kh++) {
                const float* rp = &sC1[ic][row + kh][c0];
                float2 p0 = *(const float2*)rp;
                float2 p1 = *(const float2*)(rp + 2);
                float2 p2 = *(const float2*)(rp + 4);
                float v[6] = {p0.x, p0.y, p1.x, p1.y, p2.x, p2.y};
                #pragma unroll
                for (int kw = 0; kw < 5; kw++) {
                    const float4* wp = (const float4*)&sW2[((ic * 3 + kh) * 5 + kw) * 8];
                    float4 wa = wp[0], wb = wp[1];
                    float wv[8] = {wa.x, wa.y, wa.z, wa.w, wb.x, wb.y, wb.z, wb.w};
                    #pragma unroll
                    for (int oc = 0; oc < 8; oc++) {
                        acc[oc][0] = fmaf(v[kw],     wv[oc], acc[oc][0]);
                        acc[oc][1] = fmaf(v[kw + 1], wv[oc], acc[oc][1]);
                    }
                }
            }
        }
        float s[8];
        #pragma unroll
        for (int oc = 0; oc < 8; oc++)
            s[oc] = fmaxf(acc[oc][0], 0.f) + fmaxf(acc[oc][1], 0.f);
        // warp tree-reduce all 8 channels
        #pragma unroll
        for (int off = 16; off; off >>= 1) {
            #pragma unroll
            for (int oc = 0; oc < 8; oc++)
                s[oc] += __shfl_down_sync(0xffffffffu, s[oc], off);
        }
        if ((tid & 31) == 0) {
            int wz = tid >> 5;
            #pragma unroll
            for (int oc = 0; oc < 8; oc++) sRed[wz][oc] = s[oc];
        }
    }
    __syncthreads();

    // deterministic partial write: one fixed slot per block (no atomics)
    if (tid < 8) {
        float t = 0.f;
        #pragma unroll
        for (int wz = 0; wz < 8; wz++) t += sRed[wz][tid];
        const int ph = by >> 2, sub  = by & 3;     // pool row block = 32 rows = 4 tiles
        const int pw = bx / 6,  subx = bx - pw * 6; // pool col block = 384 cols = 6 tiles
        g_partial[(((b * 8 + tid) * 4 + ph) * 4 + pw) * NCONTRIB + sub * 6 + subx] = t;
    }
}

// ---------------------------------------------------------------------------
// Head: three 32x256x512 GEMMs + pooled@W_res + combine. sconv branch == b_proj.
// grid (6, 32), 256 thr; block bx handles cols [bx*256, +256) of the 1536 output.
// ---------------------------------------------------------------------------
__global__ __launch_bounds__(256)
void head_kernel(const float* __restrict__ distance,
                 const float* __restrict__ azimuth,
                 const float* __restrict__ elevation,
                 const float* __restrict__ W_dist, const float* __restrict__ b_dist,
                 const float* __restrict__ W_az,   const float* __restrict__ b_az,
                 const float* __restrict__ W_el,   const float* __restrict__ b_el,
                 const float* __restrict__ W_res,  const float* __restrict__ b_res,
                 const float* __restrict__ b_proj,
                 const float* __restrict__ cnn_gain,
                 const float* __restrict__ sconv_gain,
                 float* __restrict__ out)
{
    __shared__ float sv[256];     // input vector for this batch/branch
    __shared__ float sp[128];     // pooled means (elev branch only)

    const int tid = threadIdx.x;
    const int b   = blockIdx.y;
    const int seg = blockIdx.x;        // 0..5
    const int col = seg * 256 + tid;   // 0..1535
    const int branch = seg >> 1;       // 0=dist 1=az 2=elev (uniform per block)

    const float* vec = (branch == 0) ? distance : (branch == 1) ? azimuth : elevation;
    sv[tid] = vec[b * 256 + tid];

    if (branch == 2 && tid < 128) {
        const float* pp = g_partial + (b * 128 + tid) * NCONTRIB;
        float t = 0.f;
        #pragma unroll
        for (int i = 0; i < NCONTRIB; i++) t += pp[i];
        sp[tid] = t * (1.0f / (32.0f * 384.0f));   // block-mean normalization
    }
    __syncthreads();

    const int j = col & 511;
    const float* Wm = (branch == 0) ? W_dist : (branch == 1) ? W_az : W_el;
    float acc = 0.f;
    #pragma unroll 8
    for (int i = 0; i < 256; i++)
        acc = fmaf(sv[i], Wm[i * 512 + j], acc);

    float r;
    if (branch == 0) {
        r = fmaxf(acc + b_dist[j], 0.f);
    } else if (branch == 1) {
        r = fmaxf(acc + b_az[j], 0.f);
    } else {
        float base = fmaxf(acc + b_el[j], 0.f);
        float lr = 0.f;
        #pragma unroll 8
        for (int k = 0; k < 128; k++)
            lr = fmaf(sp[k], W_res[k * 512 + j], lr);
        lr += b_res[j];
        float cs = 0.5f / (1.0f + expf(-cnn_gain[0]));
        float ss = 0.4f / (1.0f + expf(-sconv_gain[0]));
        // spiking LSTM output is provably all-zero -> sconv_res == b_proj
        r = fmaxf(base + cs * lr + ss * b_proj[j], 0.f);
    }
    out[b * 1536 + col] = r;
}

// ---------------------------------------------------------------------------
extern "C" void kernel_launch(void* const* d_in, const int* in_sizes, int n_in,
                              void* d_out, int out_size)
{
    const float* distance   = (const float*)d_in[0];
    const float* azimuth    = (const float*)d_in[1];
    const float* elevation  = (const float*)d_in[2];
    const float* rspikes    = (const float*)d_in[3];
    const float* W_dist     = (const float*)d_in[4];
    const float* b_dist     = (const float*)d_in[5];
    const float* W_az       = (const float*)d_in[6];
    const float* b_az       = (const float*)d_in[7];
    const float* W_el       = (const float*)d_in[8];
    const float* b_el       = (const float*)d_in[9];
    const float* conv1_w    = (const float*)d_in[10];
    const float* conv1_b    = (const float*)d_in[11];
    const float* conv2_w    = (const float*)d_in[12];
    const float* conv2_b    = (const float*)d_in[13];
    const float* W_res      = (const float*)d_in[14];
    const float* b_res      = (const float*)d_in[15];
    // d_in[16] sconv_w, d_in[17] sconv_b, d_in[18] W_proj: provably unused
    const float* b_proj     = (const float*)d_in[19];
    const float* cnn_gain   = (const float*)d_in[20];
    const float* sconv_gain = (const float*)d_in[21];

    dim3 gconv(GX, GY, BATCH);              // 24 x 16 x 32
    conv_fused_kernel<<<gconv, 256>>>(rspikes, conv1_w, conv1_b, conv2_w, conv2_b);

    dim3 ghead(6, BATCH);
    head_kernel<<<ghead, 256>>>(distance, azimuth, elevation,
                                W_dist, b_dist, W_az, b_az, W_el, b_el,
                                W_res, b_res, b_proj, cnn_gain, sconv_gain,
                                (float*)d_out);
}

// round 2
// speedup vs baseline: 1.2430x; 1.2430x over previous
#include <cuda_runtime.h>
#include <math.h>

// ---------------------------------------------------------------------------
// CombinedElevationEncoder — fused, FFMA2-packed (fma.rn.f32x2) version.
//
// Insight 1: dual-CNN branch only consumed through (4,4) block-mean pool ->
//            fuse conv1+relu+conv2+relu+pool, activations never touch GMEM.
// Insight 2: spiking LSTM emits spike(mem-1) with mem = sig(o)*tanh(syn) <= 1
//            -> all spikes exactly 0 -> sconv_res == b_proj; T=128 scan skipped.
// R2: packed f32x2 FMA over output-channel pairs (2 FLOP/instr), 16-row tiles
//     to cut conv1 halo redundancy 33% -> 19.5%.
// ---------------------------------------------------------------------------

#define BATCH 32
#define HH    128
#define WW    1536
#define TH    16         // conv output rows per block
#define TW    64         // conv output cols per block
#define GX    (WW / TW)  // 24
#define GY    (HH / TH)  // 8
#define NCONTRIB 12      // (32/TH)*(384/TW) = 2*6 contributing blocks per pool cell

// dynamic smem layout (floats)
#define SIN_ROWS 22
#define SIN_STR  76
#define SC1_ROWS 18
#define SC1_STR  72
#define OFF_SIN  0
#define OFF_SC1  (OFF_SIN + 2 * SIN_ROWS * SIN_STR)        // 3344
#define OFF_W1   (OFF_SC1 + 8 * SC1_ROWS * SC1_STR)        // +10368
#define OFF_W2   (OFF_W1 + 560)
#define OFF_B1   (OFF_W2 + 960)
#define OFF_B2   (OFF_B1 + 8)
#define OFF_RED  (OFF_B2 + 8)
#define SMEM_FLOATS (OFF_RED + 16 * 8)
#define SMEM_BYTES  (SMEM_FLOATS * 4)                      // 61504

// partial pooled sums: [b][oc][ph][pw][contrib]
__device__ float g_partial[BATCH * 8 * 4 * 4 * NCONTRIB];

// ---- packed f32x2 helpers (sm_100+) ----
__device__ __forceinline__ unsigned long long fma2(unsigned long long a,
                                                   unsigned long long b,
                                                   unsigned long long c) {
    unsigned long long d;
    asm("fma.rn.f32x2 %0, %1, %2, %3;" : "=l"(d) : "l"(a), "l"(b), "l"(c));
    return d;
}
__device__ __forceinline__ unsigned long long dup2(float x) {
    unsigned long long d;
    asm("mov.b64 %0, {%1, %1};" : "=l"(d) : "f"(x));
    return d;
}
__device__ __forceinline__ unsigned long long pk2(float lo, float hi) {
    unsigned long long d;
    asm("mov.b64 %0, {%1, %2};" : "=l"(d) : "f"(lo), "f"(hi));
    return d;
}
__device__ __forceinline__ float2 unpk(unsigned long long a) {
    float2 r;
    asm("mov.b64 {%0, %1}, %2;" : "=f"(r.x), "=f"(r.y) : "l"(a));
    return r;
}

// ---------------------------------------------------------------------------
// Fused conv1(2->8,5x7,pad 2,3)+ReLU + conv2(8->8,3x5,pad 1,2)+ReLU + pool.
// 512 threads; tile 16x64 outputs.
// ---------------------------------------------------------------------------
__global__ __launch_bounds__(512)
void conv_fused_kernel(const float* __restrict__ x,      // [B,2,H,W]
                       const float* __restrict__ w1,     // [8,2,5,7]
                       const float* __restrict__ b1,     // [8]
                       const float* __restrict__ w2,     // [8,8,3,5]
                       const float* __restrict__ b2)     // [8]
{
    extern __shared__ __align__(16) float dsm[];
    float* sIn = dsm + OFF_SIN;   // [2][22][76]
    float* sC1 = dsm + OFF_SC1;   // [8][18][72]
    float* sW1 = dsm + OFF_W1;    // [ic][kh][kw][oc] 2*5*7*8
    float* sW2 = dsm + OFF_W2;    // [ic][kh][kw][oc] 8*3*5*8
    float* sB1 = dsm + OFF_B1;
    float* sB2 = dsm + OFF_B2;
    float* sRed = dsm + OFF_RED;  // [16 warps][8 oc]

    const int tid = threadIdx.x;
    const int bx = blockIdx.x, by = blockIdx.y, b = blockIdx.z;
    const int h0 = by * TH - 3;   // input row origin (conv2 needs conv1 rows -1..+16)
    const int w0 = bx * TW - 5;   // input col origin

    // ---- repack weights into smem as [ic][kh][kw][oc] ----
    for (int idx = tid; idx < 560; idx += 512) {
        int oc = idx & 7; int t = idx >> 3;
        int kw = t % 7; t /= 7;
        int kh = t % 5; int ic = t / 5;
        sW1[idx] = w1[((oc * 2 + ic) * 5 + kh) * 7 + kw];
    }
    for (int idx = tid; idx < 960; idx += 512) {
        int oc = idx & 7; int t = idx >> 3;
        int kw = t % 5; t /= 5;
        int kh = t % 3; int ic = t / 3;
        sW2[idx] = w2[((oc * 8 + ic) * 3 + kh) * 5 + kw];
    }
    if (tid < 8) { sB1[tid] = b1[tid]; sB2[tid] = b2[tid]; }

    // ---- load input tile (zero-padded) ----
    const float* xb = x + (size_t)b * 2 * HH * WW;
    for (int idx = tid; idx < 2 * SIN_ROWS * 74; idx += 512) {
        int c = idx % 74; int t = idx / 74;
        int r = t % SIN_ROWS; int ic = t / SIN_ROWS;
        int gh = h0 + r, gw = w0 + c;
        float v = 0.f;
        if (gh >= 0 && gh < HH && gw >= 0 && gw < WW)
            v = xb[(ic * HH + gh) * WW + gw];
        sIn[(ic * SIN_ROWS + r) * SIN_STR + c] = v;
    }
    __syncthreads();

    // ---- conv1 + ReLU: 18 rows x 68 cols x 8ch; 4 cols/thread, oc-paired ----
    if (tid < 306) {                        // 18 rows * 17 col-groups
        const int r  = tid / 17;
        const int c0 = (tid % 17) * 4;
        unsigned long long accp[4][4];       // [oc pair][col]
        #pragma unroll
        for (int p = 0; p < 4; p++) {
            unsigned long long bb = pk2(sB1[2 * p], sB1[2 * p + 1]);
            accp[p][0] = bb; accp[p][1] = bb; accp[p][2] = bb; accp[p][3] = bb;
        }
        #pragma unroll
        for (int ic = 0; ic < 2; ic++) {
            #pragma unroll
            for (int kh = 0; kh < 5; kh++) {
                const float* rp = &sIn[(ic * SIN_ROWS + r + kh) * SIN_STR + c0];
                float4 q0 = *(const float4*)rp;
                float4 q1 = *(const float4*)(rp + 4);
                float2 q2 = *(const float2*)(rp + 8);
                unsigned long long vd[10];
                vd[0] = dup2(q0.x); vd[1] = dup2(q0.y); vd[2] = dup2(q0.z); vd[3] = dup2(q0.w);
                vd[4] = dup2(q1.x); vd[5] = dup2(q1.y); vd[6] = dup2(q1.z); vd[7] = dup2(q1.w);
                vd[8] = dup2(q2.x); vd[9] = dup2(q2.y);
                #pragma unroll
                for (int kw = 0; kw < 7; kw++) {
                    const ulonglong2* wq = (const ulonglong2*)&sW1[((ic * 5 + kh) * 7 + kw) * 8];
                    ulonglong2 a0 = wq[0], a1 = wq[1];
                    unsigned long long wp0 = a0.x, wp1 = a0.y, wp2 = a1.x, wp3 = a1.y;
                    #pragma unroll
                    for (int col = 0; col < 4; col++) {
                        unsigned long long vv = vd[kw + col];
                        accp[0][col] = fma2(vv, wp0, accp[0][col]);
                        accp[1][col] = fma2(vv, wp1, accp[1][col]);
                        accp[2][col] = fma2(vv, wp2, accp[2][col]);
                        accp[3][col] = fma2(vv, wp3, accp[3][col]);
                    }
                }
            }
        }
        #pragma unroll
        for (int p = 0; p < 4; p++) {
            #pragma unroll
            for (int col = 0; col < 4; col++) {
                float2 v2 = unpk(accp[p][col]);
                sC1[((2 * p)     * SC1_ROWS + r) * SC1_STR + c0 + col] = fmaxf(v2.x, 0.f);
                sC1[((2 * p + 1) * SC1_ROWS + r) * SC1_STR + c0 + col] = fmaxf(v2.y, 0.f);
            }
        }
    }
    __syncthreads();

    // ---- conv2 + ReLU + pool partial: 16 rows x 64 cols; 2 cols/thread ----
    {
        const int row = tid >> 5;            // 0..15
        const int c0  = (tid & 31) * 2;      // 0..62
        unsigned long long accp[4][2];       // [oc pair][col]
        #pragma unroll
        for (int p = 0; p < 4; p++) {
            unsigned long long bb = pk2(sB2[2 * p], sB2[2 * p + 1]);
            accp[p][0] = bb; accp[p][1] = bb;
        }
        #pragma unroll
        for (int ic = 0; ic < 8; ic++) {
            #pragma unroll
            for (int kh = 0; kh < 3; kh++) {
                const float* rp = &sC1[(ic * SC1_ROWS + row + kh) * SC1_STR + c0];
                float2 p0 = *(const float2*)rp;
                float2 p1 = *(const float2*)(rp + 2);
                float2 p2 = *(const float2*)(rp + 4);
                unsigned long long vd[6];
                vd[0] = dup2(p0.x); vd[1] = dup2(p0.y);
                vd[2] = dup2(p1.x); vd[3] = dup2(p1.y);
                vd[4] = dup2(p2.x); vd[5] = dup2(p2.y);
                #pragma unroll
                for (int kw = 0; kw < 5; kw++) {
                    const ulonglong2* wq = (const ulonglong2*)&sW2[((ic * 3 + kh) * 5 + kw) * 8];
                    ulonglong2 a0 = wq[0], a1 = wq[1];
                    unsigned long long wp0 = a0.x, wp1 = a0.y, wp2 = a1.x, wp3 = a1.y;
                    #pragma unroll
                    for (int c = 0; c < 2; c++) {
                        unsigned long long vv = vd[kw + c];
                        accp[0][c] = fma2(vv, wp0, accp[0][c]);
                        accp[1][c] = fma2(vv, wp1, accp[1][c]);
                        accp[2][c] = fma2(vv, wp2, accp[2][c]);
                        accp[3][c] = fma2(vv, wp3, accp[3][c]);
                    }
                }
            }
        }
        float s[8];
        #pragma unroll
        for (int p = 0; p < 4; p++) {
            float2 a = unpk(accp[p][0]);
            float2 c = unpk(accp[p][1]);
            s[2 * p]     = fmaxf(a.x, 0.f) + fmaxf(c.x, 0.f);
            s[2 * p + 1] = fmaxf(a.y, 0.f) + fmaxf(c.y, 0.f);
        }
        #pragma unroll
        for (int off = 16; off; off >>= 1) {
            #pragma unroll
            for (int oc = 0; oc < 8; oc++)
                s[oc] += __shfl_down_sync(0xffffffffu, s[oc], off);
        }
        if ((tid & 31) == 0) {
            int wz = tid >> 5;
            #pragma unroll
            for (int oc = 0; oc < 8; oc++) sRed[wz * 8 + oc] = s[oc];
        }
    }
    __syncthreads();

    // deterministic partial write: one fixed slot per block (no atomics)
    if (tid < 8) {
        float t = 0.f;
        #pragma unroll
        for (int wz = 0; wz < 16; wz++) t += sRed[wz * 8 + tid];
        const int ph = by >> 1, sub  = by & 1;      // pool row block = 32 rows = 2 tiles
        const int pw = bx / 6,  subx = bx - pw * 6; // pool col block = 384 cols = 6 tiles
        g_partial[(((b * 8 + tid) * 4 + ph) * 4 + pw) * NCONTRIB + sub * 6 + subx] = t;
    }
}

// ---------------------------------------------------------------------------
// Head: three 32x256x512 GEMMs + pooled@W_res + combine. sconv branch == b_proj.
// ---------------------------------------------------------------------------
__global__ __launch_bounds__(256)
void head_kernel(const float* __restrict__ distance,
                 const float* __restrict__ azimuth,
                 const float* __restrict__ elevation,
                 const float* __restrict__ W_dist, const float* __restrict__ b_dist,
                 const float* __restrict__ W_az,   const float* __restrict__ b_az,
                 const float* __restrict__ W_el,   const float* __restrict__ b_el,
                 const float* __restrict__ W_res,  const float* __restrict__ b_res,
                 const float* __restrict__ b_proj,
                 const float* __restrict__ cnn_gain,
                 const float* __restrict__ sconv_gain,
                 float* __restrict__ out)
{
    __shared__ float sv[256];     // input vector for this batch/branch
    __shared__ float sp[128];     // pooled means (elev branch only)

    const int tid = threadIdx.x;
    const int b   = blockIdx.y;
    const int seg = blockIdx.x;        // 0..5
    const int col = seg * 256 + tid;   // 0..1535
    const int branch = seg >> 1;       // 0=dist 1=az 2=elev (uniform per block)

    const float* vec = (branch == 0) ? distance : (branch == 1) ? azimuth : elevation;
    sv[tid] = vec[b * 256 + tid];

    if (branch == 2 && tid < 128) {
        const float* pp = g_partial + (b * 128 + tid) * NCONTRIB;
        float t = 0.f;
        #pragma unroll
        for (int i = 0; i < NCONTRIB; i++) t += pp[i];
        sp[tid] = t * (1.0f / (32.0f * 384.0f));   // block-mean normalization
    }
    __syncthreads();

    const int j = col & 511;
    const float* Wm = (branch == 0) ? W_dist : (branch == 1) ? W_az : W_el;
    float acc0 = 0.f, acc1 = 0.f;
    #pragma unroll 8
    for (int i = 0; i < 256; i += 2) {
        acc0 = fmaf(sv[i],     Wm[i * 512 + j],       acc0);
        acc1 = fmaf(sv[i + 1], Wm[(i + 1) * 512 + j], acc1);
    }
    float acc = acc0 + acc1;

    float r;
    if (branch == 0) {
        r = fmaxf(acc + b_dist[j], 0.f);
    } else if (branch == 1) {
        r = fmaxf(acc + b_az[j], 0.f);
    } else {
        float base = fmaxf(acc + b_el[j], 0.f);
        float lr0 = 0.f, lr1 = 0.f;
        #pragma unroll 8
        for (int k = 0; k < 128; k += 2) {
            lr0 = fmaf(sp[k],     W_res[k * 512 + j],       lr0);
            lr1 = fmaf(sp[k + 1], W_res[(k + 1) * 512 + j], lr1);
        }
        float lr = lr0 + lr1 + b_res[j];
        float cs = 0.5f / (1.0f + expf(-cnn_gain[0]));
        float ss = 0.4f / (1.0f + expf(-sconv_gain[0]));
        // spiking LSTM output is provably all-zero -> sconv_res == b_proj
        r = fmaxf(base + cs * lr + ss * b_proj[j], 0.f);
    }
    out[b * 1536 + col] = r;
}

// ---------------------------------------------------------------------------
extern "C" void kernel_launch(void* const* d_in, const int* in_sizes, int n_in,
                              void* d_out, int out_size)
{
    const float* distance   = (const float*)d_in[0];
    const float* azimuth    = (const float*)d_in[1];
    const float* elevation  = (const float*)d_in[2];
    const float* rspikes    = (const float*)d_in[3];
    const float* W_dist     = (const float*)d_in[4];
    const float* b_dist     = (const float*)d_in[5];
    const float* W_az       = (const float*)d_in[6];
    const float* b_az       = (const float*)d_in[7];
    const float* W_el       = (const float*)d_in[8];
    const float* b_el       = (const float*)d_in[9];
    const float* conv1_w    = (const float*)d_in[10];
    const float* conv1_b    = (const float*)d_in[11];
    const float* conv2_w    = (const float*)d_in[12];
    const float* conv2_b    = (const float*)d_in[13];
    const float* W_res      = (const float*)d_in[14];
    const float* b_res      = (const float*)d_in[15];
    // d_in[16] sconv_w, d_in[17] sconv_b, d_in[18] W_proj: provably unused
    const float* b_proj     = (const float*)d_in[19];
    const float* cnn_gain   = (const float*)d_in[20];
    const float* sconv_gain = (const float*)d_in[21];

    cudaFuncSetAttribute(conv_fused_kernel,
                         cudaFuncAttributeMaxDynamicSharedMemorySize, SMEM_BYTES);

    dim3 gconv(GX, GY, BATCH);              // 24 x 8 x 32
    conv_fused_kernel<<<gconv, 512, SMEM_BYTES>>>(rspikes, conv1_w, conv1_b,
                                                  conv2_w, conv2_b);

    dim3 ghead(6, BATCH);
    head_kernel<<<ghead, 256>>>(distance, azimuth, elevation,
                                W_dist, b_dist, W_az, b_az, W_el, b_el,
                                W_res, b_res, b_proj, cnn_gain, sconv_gain,
                                (float*)d_out);
}

// round 4
// speedup vs baseline: 1.4843x; 1.1941x over previous
#include <cuda_runtime.h>
#include <math.h>
#include <stdint.h>

// ---------------------------------------------------------------------------
// CombinedElevationEncoder — conv1 FFMA2, conv2 via warp-level mma.sync tf32.
// (tcgen05 is unavailable: harness PTX target is compute_100, not 100a.)
//
// Insight 1: dual-CNN branch only consumed through (4,4) block-mean pool ->
//            fuse conv1+relu+conv2+relu+pool; activations never touch GMEM.
// Insight 2: spiking LSTM emits spike(mem-1), mem = sig(o)*tanh(syn) <= 1
//            -> all spikes exactly 0 -> sconv_res == b_proj; scan skipped.
// R4: conv2 as tap-split m16n8k8 tf32 mma.sync with register accumulators.
//     conv1 out stored [pos][ic8] with ic permuted [0,4,1,5,2,6,3,7] so each
//     A-fragment thread-pair (k, k+4) is one LDS.64 and warp A loads are
//     perfectly linear (lane*8B).
// ---------------------------------------------------------------------------

#define BATCH 32
#define HH    128
#define WW    1536
#define TH    16
#define TW    64
#define GX    (WW / TW)  // 24
#define GY    (HH / TH)  // 8
#define NCONTRIB 12

// smem float offsets
#define SIN_ROWS 22
#define SIN_STR  76
#define OFF_SIN  0
#define OFF_C1   (OFF_SIN + 2 * SIN_ROWS * SIN_STR)   // 3344 ; [18*72 pos][8]
#define OFF_W1   (OFF_C1 + 18 * 72 * 8)               // 13712
#define OFF_W2M  (OFF_W1 + 560)                       // 14272 ; [tap15][k8][oc8]
#define OFF_B1   (OFF_W2M + 960)                      // 15232
#define OFF_B2   (OFF_B1 + 8)
#define OFF_RED  (OFF_B2 + 8)                         // 15248 ; [16][8]
#define SMEM_FLOATS (OFF_RED + 128)
#define SMEM_BYTES  (SMEM_FLOATS * 4)                 // ~61.5KB

// partial pooled sums: [b][oc][ph][pw][contrib]
__device__ float g_partial[BATCH * 8 * 4 * 4 * NCONTRIB];

// ---- packed f32x2 helpers ----
__device__ __forceinline__ unsigned long long fma2(unsigned long long a,
                                                   unsigned long long b,
                                                   unsigned long long c) {
    unsigned long long d;
    asm("fma.rn.f32x2 %0, %1, %2, %3;" : "=l"(d) : "l"(a), "l"(b), "l"(c));
    return d;
}
__device__ __forceinline__ unsigned long long dup2(float x) {
    unsigned long long d;
    asm("mov.b64 %0, {%1, %1};" : "=l"(d) : "f"(x));
    return d;
}
__device__ __forceinline__ unsigned long long pk2(float lo, float hi) {
    unsigned long long d;
    asm("mov.b64 %0, {%1, %2};" : "=l"(d) : "f"(lo), "f"(hi));
    return d;
}
__device__ __forceinline__ float2 unpk(unsigned long long a) {
    float2 r;
    asm("mov.b64 {%0, %1}, %2;" : "=f"(r.x), "=f"(r.y) : "l"(a));
    return r;
}
// fp32 -> tf32 (RNA) returned as fp32 bit pattern
__device__ __forceinline__ float tf32r(float x) {
    uint32_t u;
    asm("cvt.rna.tf32.f32 %0, %1;" : "=r"(u) : "f"(x));
    return __uint_as_float(u);
}

// m16n8k8 tf32 mma with accumulate-in-place
__device__ __forceinline__ void mma_tf32(float& c0, float& c1, float& c2, float& c3,
                                         uint32_t a0, uint32_t a1, uint32_t a2, uint32_t a3,
                                         uint32_t b0, uint32_t b1) {
    asm volatile(
        "mma.sync.aligned.m16n8k8.row.col.f32.tf32.tf32.f32 "
        "{%0,%1,%2,%3}, {%4,%5,%6,%7}, {%8,%9}, {%0,%1,%2,%3};"
        : "+f"(c0), "+f"(c1), "+f"(c2), "+f"(c3)
        : "r"(a0), "r"(a1), "r"(a2), "r"(a3), "r"(b0), "r"(b1));
}

// ---------------------------------------------------------------------------
__global__ __launch_bounds__(512)
void conv_fused_kernel(const float* __restrict__ x,      // [B,2,H,W]
                       const float* __restrict__ w1,     // [8,2,5,7]
                       const float* __restrict__ b1,     // [8]
                       const float* __restrict__ w2,     // [8,8,3,5]
                       const float* __restrict__ b2)     // [8]
{
    extern __shared__ __align__(16) float dsm[];
    float* sIn  = dsm + OFF_SIN;
    float* sC1  = dsm + OFF_C1;    // [pos 18*72][8 floats, ic perm 0,4,1,5,2,6,3,7]
    float* sW1  = dsm + OFF_W1;    // [ic][kh][kw][oc]
    float* sW2m = dsm + OFF_W2M;   // [tap][k logical][oc], tf32-rounded
    float* sB1  = dsm + OFF_B1;
    float* sB2  = dsm + OFF_B2;
    float* sRed = dsm + OFF_RED;

    const int tid = threadIdx.x;
    const int wid = tid >> 5;
    const int lid = tid & 31;
    const int bx = blockIdx.x, by = blockIdx.y, b = blockIdx.z;
    const int h0 = by * TH - 3;
    const int w0 = bx * TW - 5;

    // ---- repack conv1 weights ----
    for (int idx = tid; idx < 560; idx += 512) {
        int oc = idx & 7; int t = idx >> 3;
        int kw = t % 7; t /= 7;
        int kh = t % 5; int ic = t / 5;
        sW1[idx] = w1[((oc * 2 + ic) * 5 + kh) * 7 + kw];
    }
    // ---- repack conv2 weights: sW2m[tap][k][oc], tf32-rounded ----
    for (int idx = tid; idx < 960; idx += 512) {
        int oc = idx & 7; int t = idx >> 3;
        int k = t & 7; int tap = t >> 3;       // tap = kh*5+kw, 0..14
        int kh = tap / 5, kw = tap % 5;
        sW2m[idx] = tf32r(w2[((oc * 8 + k) * 3 + kh) * 5 + kw]);
    }
    if (tid < 8) { sB1[tid] = b1[tid]; sB2[tid] = b2[tid]; }

    // ---- load input tile (zero-padded) ----
    const float* xb = x + (size_t)b * 2 * HH * WW;
    for (int idx = tid; idx < 2 * SIN_ROWS * 74; idx += 512) {
        int c = idx % 74; int t = idx / 74;
        int r = t % SIN_ROWS; int ic = t / SIN_ROWS;
        int gh = h0 + r, gw = w0 + c;
        float v = 0.f;
        if (gh >= 0 && gh < HH && gw >= 0 && gw < WW)
            v = xb[(ic * HH + gh) * WW + gw];
        sIn[(ic * SIN_ROWS + r) * SIN_STR + c] = v;
    }
    __syncthreads();

    // ---- conv1 + ReLU (FFMA2): 18 rows x 68 cols x 8ch; 4 cols/thread ----
    if (tid < 306) {
        const int r  = tid / 17;
        const int c0 = (tid % 17) * 4;
        unsigned long long accp[4][4];       // [oc pair][col]
        #pragma unroll
        for (int p = 0; p < 4; p++) {
            unsigned long long bb = pk2(sB1[2 * p], sB1[2 * p + 1]);
            accp[p][0] = bb; accp[p][1] = bb; accp[p][2] = bb; accp[p][3] = bb;
        }
        #pragma unroll
        for (int ic = 0; ic < 2; ic++) {
            #pragma unroll
            for (int kh = 0; kh < 5; kh++) {
                const float* rp = &sIn[(ic * SIN_ROWS + r + kh) * SIN_STR + c0];
                float4 q0 = *(const float4*)rp;
                float4 q1 = *(const float4*)(rp + 4);
                float2 q2 = *(const float2*)(rp + 8);
                unsigned long long vd[10];
                vd[0] = dup2(q0.x); vd[1] = dup2(q0.y); vd[2] = dup2(q0.z); vd[3] = dup2(q0.w);
                vd[4] = dup2(q1.x); vd[5] = dup2(q1.y); vd[6] = dup2(q1.z); vd[7] = dup2(q1.w);
                vd[8] = dup2(q2.x); vd[9] = dup2(q2.y);
                #pragma unroll
                for (int kw = 0; kw < 7; kw++) {
                    const ulonglong2* wq = (const ulonglong2*)&sW1[((ic * 5 + kh) * 7 + kw) * 8];
                    ulonglong2 a0 = wq[0], a1 = wq[1];
                    #pragma unroll
                    for (int col = 0; col < 4; col++) {
                        unsigned long long vv = vd[kw + col];
                        accp[0][col] = fma2(vv, a0.x, accp[0][col]);
                        accp[1][col] = fma2(vv, a0.y, accp[1][col]);
                        accp[2][col] = fma2(vv, a1.x, accp[2][col]);
                        accp[3][col] = fma2(vv, a1.y, accp[3][col]);
                    }
                }
            }
        }
        // store relu + tf32-rounded, ic physically permuted [0,4,1,5,2,6,3,7]
        #pragma unroll
        for (int col = 0; col < 4; col++) {
            int pos = r * 72 + c0 + col;
            float2 v0 = unpk(accp[0][col]);   // oc0, oc1
            float2 v1 = unpk(accp[1][col]);   // oc2, oc3
            float2 v2 = unpk(accp[2][col]);   // oc4, oc5
            float2 v3 = unpk(accp[3][col]);   // oc6, oc7
            float4 lo, hi;
            lo.x = tf32r(fmaxf(v0.x, 0.f));   // ic0
            lo.y = tf32r(fmaxf(v2.x, 0.f));   // ic4
            lo.z = tf32r(fmaxf(v0.y, 0.f));   // ic1
            lo.w = tf32r(fmaxf(v2.y, 0.f));   // ic5
            hi.x = tf32r(fmaxf(v1.x, 0.f));   // ic2
            hi.y = tf32r(fmaxf(v3.x, 0.f));   // ic6
            hi.z = tf32r(fmaxf(v1.y, 0.f));   // ic3
            hi.w = tf32r(fmaxf(v3.y, 0.f));   // ic7
            *(float4*)&sC1[pos * 8]     = lo;
            *(float4*)&sC1[pos * 8 + 4] = hi;
        }
    }
    __syncthreads();

    // ---- conv2 via mma.sync tf32: warp = output row; 4 chunks x 15 taps ----
    {
        const int row = wid;                  // 0..15
        const int g   = lid >> 2;             // group 0..7
        const int tig = lid & 3;              // thread-in-group

        // preload B fragments: b0 = W[k=tig][oc=g], b1 = W[k=tig+4][oc=g]
        uint32_t bw0[15], bw1[15];
        #pragma unroll
        for (int tap = 0; tap < 15; tap++) {
            bw0[tap] = __float_as_uint(sW2m[(tap * 8 + tig) * 8 + g]);
            bw1[tap] = __float_as_uint(sW2m[(tap * 8 + tig + 4) * 8 + g]);
        }
        const float bias0 = sB2[2 * tig];
        const float bias1 = sB2[2 * tig + 1];

        float s0 = 0.f, s1 = 0.f;
        #pragma unroll
        for (int chunk = 0; chunk < 4; chunk++) {
            float c0 = bias0, c1 = bias1, c2 = bias0, c3 = bias1;
            #pragma unroll
            for (int kh = 0; kh < 3; kh++) {
                #pragma unroll
                for (int kw = 0; kw < 5; kw++) {
                    const int tap  = kh * 5 + kw;
                    const int posb = (row + kh) * 72 + chunk * 16 + kw;
                    // A loads: thread addr = base + lane*8B (conflict-free)
                    float2 A0 = *(const float2*)&sC1[(posb + g) * 8 + 2 * tig];
                    float2 A1 = *(const float2*)&sC1[(posb + g + 8) * 8 + 2 * tig];
                    mma_tf32(c0, c1, c2, c3,
                             __float_as_uint(A0.x), __float_as_uint(A1.x),
                             __float_as_uint(A0.y), __float_as_uint(A1.y),
                             bw0[tap], bw1[tap]);
                }
            }
            s0 += fmaxf(c0, 0.f) + fmaxf(c2, 0.f);
            s1 += fmaxf(c1, 0.f) + fmaxf(c3, 0.f);
        }
        // reduce over groups g (lane bits 2..4)
        #pragma unroll
        for (int off = 4; off <= 16; off <<= 1) {
            s0 += __shfl_xor_sync(0xffffffffu, s0, off);
            s1 += __shfl_xor_sync(0xffffffffu, s1, off);
        }
        if (lid < 4) {
            sRed[wid * 8 + 2 * tig]     = s0;
            sRed[wid * 8 + 2 * tig + 1] = s1;
        }
    }
    __syncthreads();

    // deterministic partial write: one fixed slot per block (no atomics)
    if (tid < 8) {
        float t = 0.f;
        #pragma unroll
        for (int wz = 0; wz < 16; wz++) t += sRed[wz * 8 + tid];
        const int ph = by >> 1, sub  = by & 1;
        const int pw = bx / 6,  subx = bx - pw * 6;
        g_partial[(((b * 8 + tid) * 4 + ph) * 4 + pw) * NCONTRIB + sub * 6 + subx] = t;
    }
}

// ---------------------------------------------------------------------------
// Head: three 32x256x512 GEMMs + pooled@W_res + combine. sconv branch == b_proj.
// ---------------------------------------------------------------------------
__global__ __launch_bounds__(256)
void head_kernel(const float* __restrict__ distance,
                 const float* __restrict__ azimuth,
                 const float* __restrict__ elevation,
                 const float* __restrict__ W_dist, const float* __restrict__ b_dist,
                 const float* __restrict__ W_az,   const float* __restrict__ b_az,
                 const float* __restrict__ W_el,   const float* __restrict__ b_el,
                 const float* __restrict__ W_res,  const float* __restrict__ b_res,
                 const float* __restrict__ b_proj,
                 const float* __restrict__ cnn_gain,
                 const float* __restrict__ sconv_gain,
                 float* __restrict__ out)
{
    __shared__ float sv[256];
    __shared__ float sp[128];

    const int tid = threadIdx.x;
    const int b   = blockIdx.y;
    const int seg = blockIdx.x;
    const int col = seg * 256 + tid;
    const int branch = seg >> 1;

    const float* vec = (branch == 0) ? distance : (branch == 1) ? azimuth : elevation;
    sv[tid] = vec[b * 256 + tid];

    if (branch == 2 && tid < 128) {
        const float* pp = g_partial + (b * 128 + tid) * NCONTRIB;
        float t = 0.f;
        #pragma unroll
        for (int i = 0; i < NCONTRIB; i++) t += pp[i];
        sp[tid] = t * (1.0f / (32.0f * 384.0f));
    }
    __syncthreads();

    const int j = col & 511;
    const float* Wm = (branch == 0) ? W_dist : (branch == 1) ? W_az : W_el;
    float a0 = 0.f, a1 = 0.f, a2 = 0.f, a3 = 0.f;
    #pragma unroll 8
    for (int i = 0; i < 256; i += 4) {
        a0 = fmaf(sv[i],     Wm[(i)     * 512 + j], a0);
        a1 = fmaf(sv[i + 1], Wm[(i + 1) * 512 + j], a1);
        a2 = fmaf(sv[i + 2], Wm[(i + 2) * 512 + j], a2);
        a3 = fmaf(sv[i + 3], Wm[(i + 3) * 512 + j], a3);
    }
    float acc = (a0 + a1) + (a2 + a3);

    float r;
    if (branch == 0) {
        r = fmaxf(acc + b_dist[j], 0.f);
    } else if (branch == 1) {
        r = fmaxf(acc + b_az[j], 0.f);
    } else {
        float base = fmaxf(acc + b_el[j], 0.f);
        float l0 = 0.f, l1 = 0.f, l2 = 0.f, l3 = 0.f;
        #pragma unroll 4
        for (int k = 0; k < 128; k += 4) {
            l0 = fmaf(sp[k],     W_res[(k)     * 512 + j], l0);
            l1 = fmaf(sp[k + 1], W_res[(k + 1) * 512 + j], l1);
            l2 = fmaf(sp[k + 2], W_res[(k + 2) * 512 + j], l2);
            l3 = fmaf(sp[k + 3], W_res[(k + 3) * 512 + j], l3);
        }
        float lr = (l0 + l1) + (l2 + l3) + b_res[j];
        float cs = 0.5f / (1.0f + expf(-cnn_gain[0]));
        float ss = 0.4f / (1.0f + expf(-sconv_gain[0]));
        r = fmaxf(base + cs * lr + ss * b_proj[j], 0.f);
    }
    out[b * 1536 + col] = r;
}

// ---------------------------------------------------------------------------
extern "C" void kernel_launch(void* const* d_in, const int* in_sizes, int n_in,
                              void* d_out, int out_size)
{
    const float* distance   = (const float*)d_in[0];
    const float* azimuth    = (const float*)d_in[1];
    const float* elevation  = (const float*)d_in[2];
    const float* rspikes    = (const float*)d_in[3];
    const float* W_dist     = (const float*)d_in[4];
    const float* b_dist     = (const float*)d_in[5];
    const float* W_az       = (const float*)d_in[6];
    const float* b_az       = (const float*)d_in[7];
    const float* W_el       = (const float*)d_in[8];
    const float* b_el       = (const float*)d_in[9];
    const float* conv1_w    = (const float*)d_in[10];
    const float* conv1_b    = (const float*)d_in[11];
    const float* conv2_w    = (const float*)d_in[12];
    const float* conv2_b    = (const float*)d_in[13];
    const float* W_res      = (const float*)d_in[14];
    const float* b_res      = (const float*)d_in[15];
    const float* b_proj     = (const float*)d_in[19];
    const float* cnn_gain   = (const float*)d_in[20];
    const float* sconv_gain = (const float*)d_in[21];

    cudaFuncSetAttribute(conv_fused_kernel,
                         cudaFuncAttributeMaxDynamicSharedMemorySize, SMEM_BYTES);

    dim3 gconv(GX, GY, BATCH);
    conv_fused_kernel<<<gconv, 512, SMEM_BYTES>>>(rspikes, conv1_w, conv1_b,
                                                  conv2_w, conv2_b);

    dim3 ghead(6, BATCH);
    head_kernel<<<ghead, 256>>>(distance, azimuth, elevation,
                                W_dist, b_dist, W_az, b_az, W_el, b_el,
                                W_res, b_res, b_proj, cnn_gain, sconv_gain,
                                (float*)d_out);
}

// round 5
// speedup vs baseline: 3.3084x; 2.2290x over previous
#include <cuda_runtime.h>
#include <math.h>
#include <stdint.h>

// ---------------------------------------------------------------------------
// CombinedElevationEncoder — both convs on bf16 m16n8k16 mma.sync.
//
// Insight 1: dual-CNN branch only consumed through (4,4) block-mean pool ->
//            fuse conv1+relu+conv2+relu+pool; activations never touch GMEM.
// Insight 2: spiking LSTM emits spike(mem-1), mem = sig(o)*tanh(syn) <= 1
//            -> all spikes exactly 0 -> sconv_res == b_proj; scan skipped.
// R5: conv1 K=16 = (8 kw incl 1 pad) x 2 ic, one MMA per kh (5/chunk).
//     conv2 K=16 = 8 ic x 2 kw, 9 MMAs/chunk. Input binary -> bf16 exact.
//     conv1 C-fragment layout == conv2 A-fragment layout (oc pair -> ic pair),
//     so conv1 epilogue stores straight into conv2's operand layout.
// ---------------------------------------------------------------------------

#define BATCH 32
#define HH    128
#define WW    1536
#define TH    16
#define TW    64
#define GX    (WW / TW)  // 24
#define GY    (HH / TH)  // 8
#define NCONTRIB 12

#define IN_ROWS 22
#define IN_STR  88       // input tile cols (bf16x2 words, ic-interleaved)
#define C1_STR  80       // conv1 plane cols (positions per row)

// partial pooled sums: [b][oc][ph][pw][contrib]
__device__ float g_partial[BATCH * 8 * 4 * 4 * NCONTRIB];

// pack two fp32 -> bf16x2 (lo = first arg)
__device__ __forceinline__ uint32_t bfpack(float lo, float hi) {
    uint32_t d;
    asm("cvt.rn.bf16x2.f32 %0, %1, %2;" : "=r"(d) : "f"(hi), "f"(lo));
    return d;
}

// m16n8k16 bf16 mma, accumulate in place (fp32 accum)
__device__ __forceinline__ void mma_bf16(float& c0, float& c1, float& c2, float& c3,
                                         uint32_t a0, uint32_t a1, uint32_t a2, uint32_t a3,
                                         uint32_t b0, uint32_t b1) {
    asm volatile(
        "mma.sync.aligned.m16n8k16.row.col.f32.bf16.bf16.f32 "
        "{%0,%1,%2,%3}, {%4,%5,%6,%7}, {%8,%9}, {%0,%1,%2,%3};"
        : "+f"(c0), "+f"(c1), "+f"(c2), "+f"(c3)
        : "r"(a0), "r"(a1), "r"(a2), "r"(a3), "r"(b0), "r"(b1));
}

// ---------------------------------------------------------------------------
__global__ __launch_bounds__(512, 2)
void conv_fused_kernel(const float* __restrict__ x,      // [B,2,H,W]
                       const float* __restrict__ w1,     // [8,2,5,7]
                       const float* __restrict__ b1,     // [8]
                       const float* __restrict__ w2,     // [8,8,3,5]
                       const float* __restrict__ b2)     // [8]
{
    // input tile: [row 22][col 88] bf16x2 word = (ic0, ic1)
    __shared__ uint32_t sInB[IN_ROWS * IN_STR];
    // conv1 out: [18 rows * 80 cols][4 words], word tig = bf16x2 (ic 2tig, 2tig+1)
    __shared__ uint32_t sC1[18 * C1_STR * 4];
    // conv1 B table: [(kh*8 + kw)*8 + oc] = pack(w1[oc][ic0][kh][kw], w1[oc][ic1][kh][kw])
    __shared__ uint32_t sW1B[320];
    // conv2 B table: [((kh*6 + kw)*4 + tg)*8 + oc] = pack(w2[oc][2tg][kh][kw], w2[oc][2tg+1][kh][kw])
    __shared__ uint32_t sW2B[576];
    __shared__ float sB1s[8], sB2s[8];
    __shared__ float sRed[16 * 8];

    const int tid = threadIdx.x;
    const int wid = tid >> 5;
    const int lid = tid & 31;
    const int g   = lid >> 2;     // fragment group (row / N col)
    const int tig = lid & 3;      // thread in group
    const int bx = blockIdx.x, by = blockIdx.y, b = blockIdx.z;
    const int h0 = by * TH - 3;
    const int w0 = bx * TW - 5;

    // ---- build weight tables ----
    for (int idx = tid; idx < 320; idx += 512) {
        int oc = idx & 7; int t = idx >> 3;
        int kw = t & 7; int kh = t >> 3;
        float lo = 0.f, hi = 0.f;
        if (kw < 7) {
            lo = w1[((oc * 2 + 0) * 5 + kh) * 7 + kw];
            hi = w1[((oc * 2 + 1) * 5 + kh) * 7 + kw];
        }
        sW1B[idx] = bfpack(lo, hi);
    }
    for (int idx = tid; idx < 576; idx += 512) {
        int oc = idx & 7; int t = idx >> 3;
        int tg = t & 3; t >>= 2;
        int kw = t % 6; int kh = t / 6;
        float lo = 0.f, hi = 0.f;
        if (kw < 5) {
            lo = w2[((oc * 8 + 2 * tg)     * 3 + kh) * 5 + kw];
            hi = w2[((oc * 8 + 2 * tg + 1) * 3 + kh) * 5 + kw];
        }
        sW2B[idx] = bfpack(lo, hi);
    }
    if (tid < 8) { sB1s[tid] = b1[tid]; sB2s[tid] = b2[tid]; }

    // ---- load input tile, ic-interleaved bf16 (spikes are 0/1 -> exact) ----
    const float* xb = x + (size_t)b * 2 * HH * WW;
    for (int idx = tid; idx < IN_ROWS * IN_STR; idx += 512) {
        int col = idx % IN_STR, row = idx / IN_STR;
        int gh = h0 + row, gw = w0 + col;
        float v0 = 0.f, v1 = 0.f;
        if (gh >= 0 && gh < HH && gw >= 0 && gw < WW) {
            v0 = xb[gh * WW + gw];
            v1 = xb[HH * WW + gh * WW + gw];
        }
        sInB[idx] = bfpack(v0, v1);
    }
    __syncthreads();

    // ---- conv1 via mma: 90 chunks (18 rows x 5 col-chunks of 16) ----
    {
        uint32_t bf[10];
        #pragma unroll
        for (int kh = 0; kh < 5; kh++) {
            bf[kh * 2]     = sW1B[(kh * 8 + tig)     * 8 + g];
            bf[kh * 2 + 1] = sW1B[(kh * 8 + tig + 4) * 8 + g];
        }
        const float bi0 = sB1s[2 * tig], bi1 = sB1s[2 * tig + 1];

        for (int cc = wid; cc < 90; cc += 16) {
            const int r  = cc / 5;
            const int c0 = (cc % 5) * 16;
            float d0 = bi0, d1 = bi1, d2 = bi0, d3 = bi1;
            #pragma unroll
            for (int kh = 0; kh < 5; kh++) {
                const uint32_t* rp = &sInB[(r + kh) * IN_STR + c0];
                uint32_t a0 = rp[g + tig];            // m=g,   kw=tig
                uint32_t a1 = rp[g + 8 + tig];        // m=g+8
                uint32_t a2 = rp[g + tig + 4];        // kw=tig+4
                uint32_t a3 = rp[g + 8 + tig + 4];
                mma_bf16(d0, d1, d2, d3, a0, a1, a2, a3,
                         bf[kh * 2], bf[kh * 2 + 1]);
            }
            // relu + bf16 pack; C frag (oc pair at m=g, g+8) == conv2 A layout
            uint32_t lo = bfpack(fmaxf(d0, 0.f), fmaxf(d1, 0.f));
            uint32_t hi = bfpack(fmaxf(d2, 0.f), fmaxf(d3, 0.f));
            sC1[(r * C1_STR + c0 + g)     * 4 + tig] = lo;
            sC1[(r * C1_STR + c0 + g + 8) * 4 + tig] = hi;
        }
    }
    __syncthreads();

    // ---- conv2 via mma + pool partial: warp = out row, 4 col-chunks ----
    {
        uint32_t bf[18];
        #pragma unroll
        for (int kh = 0; kh < 3; kh++)
            #pragma unroll
            for (int kw6 = 0; kw6 < 6; kw6++)
                bf[kh * 6 + kw6] = sW2B[((kh * 6 + kw6) * 4 + tig) * 8 + g];
        const float bi0 = sB2s[2 * tig], bi1 = sB2s[2 * tig + 1];
        const int row = wid;

        float s0 = 0.f, s1 = 0.f;
        #pragma unroll
        for (int ch = 0; ch < 4; ch++) {
            const int c0 = ch * 16;
            float d0 = bi0, d1 = bi1, d2 = bi0, d3 = bi1;
            #pragma unroll
            for (int kh = 0; kh < 3; kh++) {
                #pragma unroll
                for (int j = 0; j < 3; j++) {
                    const int kwb = 2 * j;
                    const uint32_t* pp = &sC1[((row + kh) * C1_STR + c0 + kwb) * 4];
                    uint32_t a0 = pp[(g)     * 4 + tig];   // kw=kwb,   m=g
                    uint32_t a1 = pp[(g + 8) * 4 + tig];   // m=g+8
                    uint32_t a2 = pp[(g + 1) * 4 + tig];   // kw=kwb+1
                    uint32_t a3 = pp[(g + 9) * 4 + tig];
                    mma_bf16(d0, d1, d2, d3, a0, a1, a2, a3,
                             bf[kh * 6 + kwb], bf[kh * 6 + kwb + 1]);
                }
            }
            s0 += fmaxf(d0, 0.f) + fmaxf(d2, 0.f);
            s1 += fmaxf(d1, 0.f) + fmaxf(d3, 0.f);
        }
        // reduce over g (lane bits 2..4); s0 = oc 2tig, s1 = oc 2tig+1
        #pragma unroll
        for (int off = 4; off <= 16; off <<= 1) {
            s0 += __shfl_xor_sync(0xffffffffu, s0, off);
            s1 += __shfl_xor_sync(0xffffffffu, s1, off);
        }
        if (lid < 4) {
            sRed[wid * 8 + 2 * tig]     = s0;
            sRed[wid * 8 + 2 * tig + 1] = s1;
        }
    }
    __syncthreads();

    // deterministic partial write: one fixed slot per block (no atomics)
    if (tid < 8) {
        float t = 0.f;
        #pragma unroll
        for (int wz = 0; wz < 16; wz++) t += sRed[wz * 8 + tid];
        const int ph = by >> 1, sub  = by & 1;
        const int pw = bx / 6,  subx = bx - pw * 6;
        g_partial[(((b * 8 + tid) * 4 + ph) * 4 + pw) * NCONTRIB + sub * 6 + subx] = t;
    }
}

// ---------------------------------------------------------------------------
// Head: three 32x256x512 GEMMs + pooled@W_res + combine. sconv branch == b_proj.
// ---------------------------------------------------------------------------
__global__ __launch_bounds__(256)
void head_kernel(const float* __restrict__ distance,
                 const float* __restrict__ azimuth,
                 const float* __restrict__ elevation,
                 const float* __restrict__ W_dist, const float* __restrict__ b_dist,
                 const float* __restrict__ W_az,   const float* __restrict__ b_az,
                 const float* __restrict__ W_el,   const float* __restrict__ b_el,
                 const float* __restrict__ W_res,  const float* __restrict__ b_res,
                 const float* __restrict__ b_proj,
                 const float* __restrict__ cnn_gain,
                 const float* __restrict__ sconv_gain,
                 float* __restrict__ out)
{
    __shared__ float sv[256];
    __shared__ float sp[128];

    const int tid = threadIdx.x;
    const int b   = blockIdx.y;
    const int seg = blockIdx.x;
    const int col = seg * 256 + tid;
    const int branch = seg >> 1;

    const float* vec = (branch == 0) ? distance : (branch == 1) ? azimuth : elevation;
    sv[tid] = vec[b * 256 + tid];

    if (branch == 2 && tid < 128) {
        const float* pp = g_partial + (b * 128 + tid) * NCONTRIB;
        float t = 0.f;
        #pragma unroll
        for (int i = 0; i < NCONTRIB; i++) t += pp[i];
        sp[tid] = t * (1.0f / (32.0f * 384.0f));
    }
    __syncthreads();

    const int j = col & 511;
    const float* Wm = (branch == 0) ? W_dist : (branch == 1) ? W_az : W_el;
    float a0 = 0.f, a1 = 0.f, a2 = 0.f, a3 = 0.f;
    #pragma unroll 8
    for (int i = 0; i < 256; i += 4) {
        a0 = fmaf(sv[i],     Wm[(i)     * 512 + j], a0);
        a1 = fmaf(sv[i + 1], Wm[(i + 1) * 512 + j], a1);
        a2 = fmaf(sv[i + 2], Wm[(i + 2) * 512 + j], a2);
        a3 = fmaf(sv[i + 3], Wm[(i + 3) * 512 + j], a3);
    }
    float acc = (a0 + a1) + (a2 + a3);

    float r;
    if (branch == 0) {
        r = fmaxf(acc + b_dist[j], 0.f);
    } else if (branch == 1) {
        r = fmaxf(acc + b_az[j], 0.f);
    } else {
        float base = fmaxf(acc + b_el[j], 0.f);
        float l0 = 0.f, l1 = 0.f, l2 = 0.f, l3 = 0.f;
        #pragma unroll 4
        for (int k = 0; k < 128; k += 4) {
            l0 = fmaf(sp[k],     W_res[(k)     * 512 + j], l0);
            l1 = fmaf(sp[k + 1], W_res[(k + 1) * 512 + j], l1);
            l2 = fmaf(sp[k + 2], W_res[(k + 2) * 512 + j], l2);
            l3 = fmaf(sp[k + 3], W_res[(k + 3) * 512 + j], l3);
        }
        float lr = (l0 + l1) + (l2 + l3) + b_res[j];
        float cs = 0.5f / (1.0f + expf(-cnn_gain[0]));
        float ss = 0.4f / (1.0f + expf(-sconv_gain[0]));
        r = fmaxf(base + cs * lr + ss * b_proj[j], 0.f);
    }
    out[b * 1536 + col] = r;
}

// ---------------------------------------------------------------------------
extern "C" void kernel_launch(void* const* d_in, const int* in_sizes, int n_in,
                              void* d_out, int out_size)
{
    const float* distance   = (const float*)d_in[0];
    const float* azimuth    = (const float*)d_in[1];
    const float* elevation  = (const float*)d_in[2];
    const float* rspikes    = (const float*)d_in[3];
    const float* W_dist     = (const float*)d_in[4];
    const float* b_dist     = (const float*)d_in[5];
    const float* W_az       = (const float*)d_in[6];
    const float* b_az       = (const float*)d_in[7];
    const float* W_el       = (const float*)d_in[8];
    const float* b_el       = (const float*)d_in[9];
    const float* conv1_w    = (const float*)d_in[10];
    const float* conv1_b    = (const float*)d_in[11];
    const float* conv2_w    = (const float*)d_in[12];
    const float* conv2_b    = (const float*)d_in[13];
    const float* W_res      = (const float*)d_in[14];
    const float* b_res      = (const float*)d_in[15];
    const float* b_proj     = (const float*)d_in[19];
    const float* cnn_gain   = (const float*)d_in[20];
    const float* sconv_gain = (const float*)d_in[21];

    dim3 gconv(GX, GY, BATCH);
    conv_fused_kernel<<<gconv, 512>>>(rspikes, conv1_w, conv1_b,
                                      conv2_w, conv2_b);

    dim3 ghead(6, BATCH);
    head_kernel<<<ghead, 256>>>(distance, azimuth, elevation,
                                W_dist, b_dist, W_az, b_az, W_el, b_el,
                                W_res, b_res, b_proj, cnn_gain, sconv_gain,
                                (float*)d_out);
}

// round 6
// speedup vs baseline: 3.3348x; 1.0080x over previous
#include <cuda_runtime.h>
#include <math.h>
#include <stdint.h>

// ---------------------------------------------------------------------------
// CombinedElevationEncoder — both convs on bf16 m16n8k16 mma.sync + ldmatrix.
//
// Insight 1: dual-CNN branch only consumed through (4,4) block-mean pool ->
//            fuse conv1+relu+conv2+relu+pool; activations never touch GMEM.
// Insight 2: spiking LSTM emits spike(mem-1), mem = sig(o)*tanh(syn) <= 1
//            -> all spikes exactly 0 -> sconv_res == b_proj; scan skipped.
// R6: A fragments via ldmatrix.x4. conv2 reads sC1 (16B/pos slots) directly;
//     conv1 reads a 4x-duplicated sliding-window layout sIn4[pos]=words[p..p+3]
//     so every tile row is 16B-aligned. Head kernel 4-way k-split + LDG.128.
// ---------------------------------------------------------------------------

#define BATCH 32
#define HH    128
#define WW    1536
#define TH    16
#define TW    64
#define GX    (WW / TW)  // 24
#define GY    (HH / TH)  // 8
#define NCONTRIB 12

#define IN_ROWS 22
#define IN_STR  88       // input tile cols (bf16x2 words, ic-interleaved)
#define C1_STR  80       // conv1 plane cols (positions per row)

// dynamic smem word offsets
#define OFF_INB 0                         // [22*88] words
#define OFF_IN4 1936                      // [22*88 slots][4 words]  (16B aligned)
#define OFF_C1  9680                      // [18*80 slots][4 words]  (16B aligned)
#define OFF_W1B 15440                     // 320
#define OFF_W2B 15760                     // 576
#define OFF_B1  16336
#define OFF_B2  16344
#define OFF_RED 16352                     // 128 floats
#define SMEM_WORDS 16480
#define SMEM_BYTES (SMEM_WORDS * 4)       // 65920

// partial pooled sums: [b][oc][ph][pw][contrib]
__device__ float g_partial[BATCH * 8 * 4 * 4 * NCONTRIB];

// pack two fp32 -> bf16x2 (lo = first arg)
__device__ __forceinline__ uint32_t bfpack(float lo, float hi) {
    uint32_t d;
    asm("cvt.rn.bf16x2.f32 %0, %1, %2;" : "=r"(d) : "f"(hi), "f"(lo));
    return d;
}

// m16n8k16 bf16 mma, accumulate in place (fp32 accum)
__device__ __forceinline__ void mma_bf16(float& c0, float& c1, float& c2, float& c3,
                                         uint32_t a0, uint32_t a1, uint32_t a2, uint32_t a3,
                                         uint32_t b0, uint32_t b1) {
    asm volatile(
        "mma.sync.aligned.m16n8k16.row.col.f32.bf16.bf16.f32 "
        "{%0,%1,%2,%3}, {%4,%5,%6,%7}, {%8,%9}, {%0,%1,%2,%3};"
        : "+f"(c0), "+f"(c1), "+f"(c2), "+f"(c3)
        : "r"(a0), "r"(a1), "r"(a2), "r"(a3), "r"(b0), "r"(b1));
}

__device__ __forceinline__ void ldsm_x4(uint32_t& r0, uint32_t& r1,
                                        uint32_t& r2, uint32_t& r3, uint32_t addr) {
    asm volatile("ldmatrix.sync.aligned.m8n8.x4.shared.b16 {%0,%1,%2,%3}, [%4];"
                 : "=r"(r0), "=r"(r1), "=r"(r2), "=r"(r3) : "r"(addr));
}

__device__ __forceinline__ uint32_t smem_u32(const void* p) {
    return (uint32_t)__cvta_generic_to_shared(p);
}

// ---------------------------------------------------------------------------
__global__ __launch_bounds__(512, 2)
void conv_fused_kernel(const float* __restrict__ x,      // [B,2,H,W]
                       const float* __restrict__ w1,     // [8,2,5,7]
                       const float* __restrict__ b1,     // [8]
                       const float* __restrict__ w2,     // [8,8,3,5]
                       const float* __restrict__ b2)     // [8]
{
    extern __shared__ __align__(16) uint32_t dsm[];
    uint32_t* sInB = dsm + OFF_INB;       // [row22][col88] bf16x2 (ic0,ic1)
    uint32_t* sIn4 = dsm + OFF_IN4;       // [slot = row*88+c][4 words = cols c..c+3]
    uint32_t* sC1  = dsm + OFF_C1;        // [pos=row*80+c][4 words: tig -> ic 2tig,2tig+1]
    uint32_t* sW1B = dsm + OFF_W1B;
    uint32_t* sW2B = dsm + OFF_W2B;
    float* sB1s = (float*)(dsm + OFF_B1);
    float* sB2s = (float*)(dsm + OFF_B2);
    float* sRed = (float*)(dsm + OFF_RED);

    const int tid = threadIdx.x;
    const int wid = tid >> 5;
    const int lid = tid & 31;
    const int g   = lid >> 2;     // fragment group
    const int tig = lid & 3;      // thread in group
    const int bx = blockIdx.x, by = blockIdx.y, b = blockIdx.z;
    const int h0 = by * TH - 3;
    const int w0 = bx * TW - 5;

    // ---- build weight tables ----
    for (int idx = tid; idx < 320; idx += 512) {
        int oc = idx & 7; int t = idx >> 3;
        int kw = t & 7; int kh = t >> 3;
        float lo = 0.f, hi = 0.f;
        if (kw < 7) {
            lo = w1[((oc * 2 + 0) * 5 + kh) * 7 + kw];
            hi = w1[((oc * 2 + 1) * 5 + kh) * 7 + kw];
        }
        sW1B[idx] = bfpack(lo, hi);
    }
    for (int idx = tid; idx < 576; idx += 512) {
        int oc = idx & 7; int t = idx >> 3;
        int tg = t & 3; t >>= 2;
        int kw = t % 6; int kh = t / 6;
        float lo = 0.f, hi = 0.f;
        if (kw < 5) {
            lo = w2[((oc * 8 + 2 * tg)     * 3 + kh) * 5 + kw];
            hi = w2[((oc * 8 + 2 * tg + 1) * 3 + kh) * 5 + kw];
        }
        sW2B[idx] = bfpack(lo, hi);
    }
    if (tid < 8) { sB1s[tid] = b1[tid]; sB2s[tid] = b2[tid]; }

    // ---- load input tile, ic-interleaved bf16 (spikes 0/1 -> exact) ----
    const float* xb = x + (size_t)b * 2 * HH * WW;
    for (int idx = tid; idx < IN_ROWS * IN_STR; idx += 512) {
        int col = idx % IN_STR, row = idx / IN_STR;
        int gh = h0 + row, gw = w0 + col;
        float v0 = 0.f, v1 = 0.f;
        if (gh >= 0 && gh < HH && gw >= 0 && gw < WW) {
            v0 = xb[gh * WW + gw];
            v1 = xb[HH * WW + gh * WW + gw];
        }
        sInB[idx] = bfpack(v0, v1);
    }
    __syncthreads();

    // ---- build sIn4 sliding-window slots: slot(row,c) = words c..c+3 ----
    for (int idx = tid; idx < IN_ROWS * 84; idx += 512) {
        int c = idx % 84, row = idx / 84;
        const uint32_t* wp = &sInB[row * IN_STR + c];
        uint4 v = make_uint4(wp[0], wp[1], wp[2], wp[3]);
        *(uint4*)&sIn4[(row * IN_STR + c) * 4] = v;
    }
    __syncthreads();

    // ---- conv1 via mma + ldmatrix: 90 chunks (18 rows x 5 col-chunks) ----
    {
        uint32_t bf[10];
        #pragma unroll
        for (int kh = 0; kh < 5; kh++) {
            bf[kh * 2]     = sW1B[(kh * 8 + tig)     * 8 + g];
            bf[kh * 2 + 1] = sW1B[(kh * 8 + tig + 4) * 8 + g];
        }
        const float bi0 = sB1s[2 * tig], bi1 = sB1s[2 * tig + 1];
        // lane row offset: tiles {m0-7,k0-7},{m8-15,k0-7},{m0-7,k8-15},{m8-15,k8-15}
        const int loff1 = (lid < 16) ? lid : (lid - 12);
        const uint32_t in4_addr = smem_u32(sIn4);

        for (int cc = wid; cc < 90; cc += 16) {
            const int r  = cc / 5;
            const int c0 = (cc % 5) * 16;
            uint32_t a_addr = in4_addr + (uint32_t)((r * IN_STR + c0 + loff1) * 16);
            float d0 = bi0, d1 = bi1, d2 = bi0, d3 = bi1;
            #pragma unroll
            for (int kh = 0; kh < 5; kh++) {
                uint32_t a0, a1, a2, a3;
                ldsm_x4(a0, a1, a2, a3, a_addr);
                a_addr += IN_STR * 16;
                mma_bf16(d0, d1, d2, d3, a0, a1, a2, a3,
                         bf[kh * 2], bf[kh * 2 + 1]);
            }
            // relu + bf16 pack; C frag (oc pair at m=g,g+8) == conv2 A layout
            uint32_t lo = bfpack(fmaxf(d0, 0.f), fmaxf(d1, 0.f));
            uint32_t hi = bfpack(fmaxf(d2, 0.f), fmaxf(d3, 0.f));
            sC1[(r * C1_STR + c0 + g)     * 4 + tig] = lo;
            sC1[(r * C1_STR + c0 + g + 8) * 4 + tig] = hi;
        }
    }
    __syncthreads();

    // ---- conv2 via mma + ldmatrix + pool partial: warp = out row ----
    {
        uint32_t bf[18];
        #pragma unroll
        for (int kh = 0; kh < 3; kh++)
            #pragma unroll
            for (int kw6 = 0; kw6 < 6; kw6++)
                bf[kh * 6 + kw6] = sW2B[((kh * 6 + kw6) * 4 + tig) * 8 + g];
        const float bi0 = sB2s[2 * tig], bi1 = sB2s[2 * tig + 1];
        const int row = wid;
        // tiles: {m0-7,kw+0},{m8-15,kw+0},{m0-7,kw+1},{m8-15,kw+1}
        const int loff2 = (lid < 16) ? lid : (lid - 15);
        const uint32_t c1_addr = smem_u32(sC1);

        float s0 = 0.f, s1 = 0.f;
        #pragma unroll
        for (int ch = 0; ch < 4; ch++) {
            const int c0 = ch * 16;
            float d0 = bi0, d1 = bi1, d2 = bi0, d3 = bi1;
            #pragma unroll
            for (int kh = 0; kh < 3; kh++) {
                uint32_t base = c1_addr +
                    (uint32_t)((((row + kh) * C1_STR) + c0 + loff2) * 16);
                #pragma unroll
                for (int j = 0; j < 3; j++) {
                    uint32_t a0, a1, a2, a3;
                    ldsm_x4(a0, a1, a2, a3, base + (uint32_t)(j * 32));
                    mma_bf16(d0, d1, d2, d3, a0, a1, a2, a3,
                             bf[kh * 6 + 2 * j], bf[kh * 6 + 2 * j + 1]);
                }
            }
            s0 += fmaxf(d0, 0.f) + fmaxf(d2, 0.f);
            s1 += fmaxf(d1, 0.f) + fmaxf(d3, 0.f);
        }
        // reduce over g (lane bits 2..4); s0 = oc 2tig, s1 = oc 2tig+1
        #pragma unroll
        for (int off = 4; off <= 16; off <<= 1) {
            s0 += __shfl_xor_sync(0xffffffffu, s0, off);
            s1 += __shfl_xor_sync(0xffffffffu, s1, off);
        }
        if (lid < 4) {
            sRed[wid * 8 + 2 * tig]     = s0;
            sRed[wid * 8 + 2 * tig + 1] = s1;
        }
    }
    __syncthreads();

    // deterministic partial write: one fixed slot per block (no atomics)
    if (tid < 8) {
        float t = 0.f;
        #pragma unroll
        for (int wz = 0; wz < 16; wz++) t += sRed[wz * 8 + tid];
        const int ph = by >> 1, sub  = by & 1;
        const int pw = bx / 6,  subx = bx - pw * 6;
        g_partial[(((b * 8 + tid) * 4 + ph) * 4 + pw) * NCONTRIB + sub * 6 + subx] = t;
    }
}

// ---------------------------------------------------------------------------
// Head: 4-way k-split, float4 W loads. sconv branch == b_proj (all spikes 0).
// grid (6, 32), 256 threads: tid = ks(4) x jq(64); each jq owns 4 out cols.
// ---------------------------------------------------------------------------
__global__ __launch_bounds__(256)
void head_kernel(const float* __restrict__ distance,
                 const float* __restrict__ azimuth,
                 const float* __restrict__ elevation,
                 const float* __restrict__ W_dist, const float* __restrict__ b_dist,
                 const float* __restrict__ W_az,   const float* __restrict__ b_az,
                 const float* __restrict__ W_el,   const float* __restrict__ b_el,
                 const float* __restrict__ W_res,  const float* __restrict__ b_res,
                 const float* __restrict__ b_proj,
                 const float* __restrict__ cnn_gain,
                 const float* __restrict__ sconv_gain,
                 float* __restrict__ out)
{
    __shared__ float sv[256];
    __shared__ float sp[128];
    __shared__ float4 sacc[4][64];
    __shared__ float4 slr[4][64];

    const int tid = threadIdx.x;
    const int jq  = tid & 63;
    const int ks  = tid >> 6;          // 0..3
    const int b   = blockIdx.y;
    const int seg = blockIdx.x;        // 0..5
    const int branch = seg >> 1;       // uniform per block
    const int j = (seg & 1) * 256 + jq * 4;   // col within 512

    const float* vec = (branch == 0) ? distance : (branch == 1) ? azimuth : elevation;
    sv[tid] = vec[b * 256 + tid];

    if (branch == 2 && tid < 128) {
        const float* pp = g_partial + (b * 128 + tid) * NCONTRIB;
        float t = 0.f;
        #pragma unroll
        for (int i = 0; i < NCONTRIB; i++) t += pp[i];
        sp[tid] = t * (1.0f / (32.0f * 384.0f));
    }
    __syncthreads();

    const float* Wm = (branch == 0) ? W_dist : (branch == 1) ? W_az : W_el;
    float4 acc = make_float4(0.f, 0.f, 0.f, 0.f);
    #pragma unroll 8
    for (int k = ks * 64; k < ks * 64 + 64; k++) {
        float s = sv[k];
        float4 w = *(const float4*)&Wm[k * 512 + j];
        acc.x = fmaf(s, w.x, acc.x);
        acc.y = fmaf(s, w.y, acc.y);
        acc.z = fmaf(s, w.z, acc.z);
        acc.w = fmaf(s, w.w, acc.w);
    }
    sacc[ks][jq] = acc;

    if (branch == 2) {
        float4 lr = make_float4(0.f, 0.f, 0.f, 0.f);
        #pragma unroll 8
        for (int k = ks * 32; k < ks * 32 + 32; k++) {
            float s = sp[k];
            float4 w = *(const float4*)&W_res[k * 512 + j];
            lr.x = fmaf(s, w.x, lr.x);
            lr.y = fmaf(s, w.y, lr.y);
            lr.z = fmaf(s, w.z, lr.z);
            lr.w = fmaf(s, w.w, lr.w);
        }
        slr[ks][jq] = lr;
    }
    __syncthreads();

    if (ks == 0) {
        float4 a0 = sacc[0][jq], a1 = sacc[1][jq], a2 = sacc[2][jq], a3 = sacc[3][jq];
        float4 r;
        r.x = (a0.x + a1.x) + (a2.x + a3.x);
        r.y = (a0.y + a1.y) + (a2.y + a3.y);
        r.z = (a0.z + a1.z) + (a2.z + a3.z);
        r.w = (a0.w + a1.w) + (a2.w + a3.w);

        if (branch == 0) {
            float4 bb = *(const float4*)&b_dist[j];
            r.x = fmaxf(r.x + bb.x, 0.f); r.y = fmaxf(r.y + bb.y, 0.f);
            r.z = fmaxf(r.z + bb.z, 0.f); r.w = fmaxf(r.w + bb.w, 0.f);
        } else if (branch == 1) {
            float4 bb = *(const float4*)&b_az[j];
            r.x = fmaxf(r.x + bb.x, 0.f); r.y = fmaxf(r.y + bb.y, 0.f);
            r.z = fmaxf(r.z + bb.z, 0.f); r.w = fmaxf(r.w + bb.w, 0.f);
        } else {
            float4 bb = *(const float4*)&b_el[j];
            float4 base;
            base.x = fmaxf(r.x + bb.x, 0.f); base.y = fmaxf(r.y + bb.y, 0.f);
            base.z = fmaxf(r.z + bb.z, 0.f); base.w = fmaxf(r.w + bb.w, 0.f);
            float4 l0 = slr[0][jq], l1 = slr[1][jq], l2 = slr[2][jq], l3 = slr[3][jq];
            float4 br = *(const float4*)&b_res[j];
            float4 bp = *(const float4*)&b_proj[j];
            float cs = 0.5f / (1.0f + expf(-cnn_gain[0]));
            float ss = 0.4f / (1.0f + expf(-sconv_gain[0]));
            r.x = fmaxf(base.x + cs * ((l0.x + l1.x) + (l2.x + l3.x) + br.x) + ss * bp.x, 0.f);
            r.y = fmaxf(base.y + cs * ((l0.y + l1.y) + (l2.y + l3.y) + br.y) + ss * bp.y, 0.f);
            r.z = fmaxf(base.z + cs * ((l0.z + l1.z) + (l2.z + l3.z) + br.z) + ss * bp.z, 0.f);
            r.w = fmaxf(base.w + cs * ((l0.w + l1.w) + (l2.w + l3.w) + br.w) + ss * bp.w, 0.f);
        }
        *(float4*)&out[b * 1536 + seg * 256 + jq * 4] = r;
    }
}

// ---------------------------------------------------------------------------
extern "C" void kernel_launch(void* const* d_in, const int* in_sizes, int n_in,
                              void* d_out, int out_size)
{
    const float* distance   = (const float*)d_in[0];
    const float* azimuth    = (const float*)d_in[1];
    const float* elevation  = (const float*)d_in[2];
    const float* rspikes    = (const float*)d_in[3];
    const float* W_dist     = (const float*)d_in[4];
    const float* b_dist     = (const float*)d_in[5];
    const float* W_az       = (const float*)d_in[6];
    const float* b_az       = (const float*)d_in[7];
    const float* W_el       = (const float*)d_in[8];
    const float* b_el       = (const float*)d_in[9];
    const float* conv1_w    = (const float*)d_in[10];
    const float* conv1_b    = (const float*)d_in[11];
    const float* conv2_w    = (const float*)d_in[12];
    const float* conv2_b    = (const float*)d_in[13];
    const float* W_res      = (const float*)d_in[14];
    const float* b_res      = (const float*)d_in[15];
    const float* b_proj     = (const float*)d_in[19];
    const float* cnn_gain   = (const float*)d_in[20];
    const float* sconv_gain = (const float*)d_in[21];

    cudaFuncSetAttribute(conv_fused_kernel,
                         cudaFuncAttributeMaxDynamicSharedMemorySize, SMEM_BYTES);

    dim3 gconv(GX, GY, BATCH);
    conv_fused_kernel<<<gconv, 512, SMEM_BYTES>>>(rspikes, conv1_w, conv1_b,
                                                  conv2_w, conv2_b);

    dim3 ghead(6, BATCH);
    head_kernel<<<ghead, 256>>>(distance, azimuth, elevation,
                                W_dist, b_dist, W_az, b_az, W_el, b_el,
                                W_res, b_res, b_proj, cnn_gain, sconv_gain,
                                (float*)d_out);
}